// round 10
// baseline (speedup 1.0000x reference)
#include <cuda_runtime.h>
#include <cuda_bf16.h>

// Comparator4Bit: A,B are (N,4) float32 with values in {0,1}.
// col0 = MSB ... col3 = LSB of a 4-bit number.
// out[0:N] = (valA > valB) ? 1.0f : 0.0f;  out[N:2N] = (valA == valB) ? 1.0f : 0.0f
//
// HBM-bound streaming at the mixed read/write DRAM ceiling (~6.1 TB/s).
// Best measured shape (R7/R9): flat launch, 512-thread blocks, 2 rows/thread,
// 4x LDG.128 front-batched, float2 __stcs stores. This round: __ldcs
// (evict-first) loads too — single-touch input shouldn't occupy L2 against
// the write stream. u64 lexicographic unsigned compare: words are
// 0x0/0x3F800000, so (col0<<32|col1, col2<<32|col3) ordering == 4-bit order.

static __device__ __forceinline__ void row_keys(const uint4 v,
                                                unsigned long long& hi,
                                                unsigned long long& lo) {
    hi = ((unsigned long long)v.x << 32) | v.y;   // col0 (MSB), col1
    lo = ((unsigned long long)v.z << 32) | v.w;   // col2, col3 (LSB)
}

__global__ void __launch_bounds__(512, 4)
comparator4bit_kernel(const uint4* __restrict__ A4,
                      const uint4* __restrict__ B4,
                      float2* __restrict__ out_gt2,
                      float2* __restrict__ out_eq2,
                      int n_units)   // n_rows / 2 work units
{
    int t = blockIdx.x * blockDim.x + threadIdx.x;
    if (t >= n_units) return;
    int base = t * 2;

    // Front-batch all 4 loads for max MLP (evict-first: single-touch stream).
    uint4 a0 = __ldcs(A4 + base + 0);
    uint4 a1 = __ldcs(A4 + base + 1);
    uint4 b0 = __ldcs(B4 + base + 0);
    uint4 b1 = __ldcs(B4 + base + 1);

    unsigned long long ah0, al0, bh0, bl0, ah1, al1, bh1, bl1;
    row_keys(a0, ah0, al0);  row_keys(b0, bh0, bl0);
    row_keys(a1, ah1, al1);  row_keys(b1, bh1, bl1);

    bool he0 = (ah0 == bh0);
    bool he1 = (ah1 == bh1);

    float2 gt, eq;
    gt.x = ((ah0 > bh0) || (he0 && al0 > bl0)) ? 1.0f : 0.0f;
    eq.x = (he0 && al0 == bl0) ? 1.0f : 0.0f;
    gt.y = ((ah1 > bh1) || (he1 && al1 > bl1)) ? 1.0f : 0.0f;
    eq.y = (he1 && al1 == bl1) ? 1.0f : 0.0f;

    __stcs(out_gt2 + t, gt);
    __stcs(out_eq2 + t, eq);
}

extern "C" void kernel_launch(void* const* d_in, const int* in_sizes, int n_in,
                              void* d_out, int out_size) {
    const float* A = (const float*)d_in[0];
    const float* B = (const float*)d_in[1];
    float* out = (float*)d_out;

    int n_rows = in_sizes[0] / 4;   // (N,4) float32 -> N rows
    int n_units = n_rows / 2;       // 2 rows per thread

    float* out_gt = out;            // [0:N)
    float* out_eq = out + n_rows;   // [N:2N)

    const int threads = 512;
    int blocks = (n_units + threads - 1) / threads;

    comparator4bit_kernel<<<blocks, threads>>>(
        (const uint4*)A, (const uint4*)B,
        (float2*)out_gt, (float2*)out_eq, n_units);
}

// round 11
// speedup vs baseline: 1.0011x; 1.0011x over previous
#include <cuda_runtime.h>
#include <cuda_bf16.h>

// Comparator4Bit: A,B are (N,4) float32 with values in {0,1}.
// col0 = MSB ... col3 = LSB of a 4-bit number.
// out[0:N] = (valA > valB) ? 1.0f : 0.0f;  out[N:2N] = (valA == valB) ? 1.0f : 0.0f
//
// FINAL — measured optimum over 9 structural variants (all axes explored):
//   rows/thread {1,2,4} -> 2;  block {256,512} -> 512;
//   load policy {default,.cg,.cs} -> default;  store policy {default,.cs} -> .cs;
//   launch {flat,persistent} -> flat;  compare {float,uint-shift,u64-lex} -> u64-lex.
// HBM-bound streaming: 128 MiB read + 32 MiB write, pinned at the mixed
// read/write DRAM turnaround ceiling (24.2us ncu, 6.13 TB/s, 77.5% DRAM).
// u64 lexicographic unsigned compare: words are 0x0/0x3F800000, so
// (col0<<32|col1, col2<<32|col3) unsigned ordering == 4-bit numeric ordering.

static __device__ __forceinline__ void row_keys(const uint4 v,
                                                unsigned long long& hi,
                                                unsigned long long& lo) {
    hi = ((unsigned long long)v.x << 32) | v.y;   // col0 (MSB), col1
    lo = ((unsigned long long)v.z << 32) | v.w;   // col2, col3 (LSB)
}

__global__ void __launch_bounds__(512, 4)
comparator4bit_kernel(const uint4* __restrict__ A4,
                      const uint4* __restrict__ B4,
                      float2* __restrict__ out_gt2,
                      float2* __restrict__ out_eq2,
                      int n_units)   // n_rows / 2 work units
{
    int t = blockIdx.x * blockDim.x + threadIdx.x;
    if (t >= n_units) return;
    int base = t * 2;

    // Front-batch all 4 loads for max MLP (default cache policy — measured best).
    uint4 a0 = A4[base + 0];
    uint4 a1 = A4[base + 1];
    uint4 b0 = B4[base + 0];
    uint4 b1 = B4[base + 1];

    unsigned long long ah0, al0, bh0, bl0, ah1, al1, bh1, bl1;
    row_keys(a0, ah0, al0);  row_keys(b0, bh0, bl0);
    row_keys(a1, ah1, al1);  row_keys(b1, bh1, bl1);

    bool he0 = (ah0 == bh0);
    bool he1 = (ah1 == bh1);

    float2 gt, eq;
    gt.x = ((ah0 > bh0) || (he0 && al0 > bl0)) ? 1.0f : 0.0f;
    eq.x = (he0 && al0 == bl0) ? 1.0f : 0.0f;
    gt.y = ((ah1 > bh1) || (he1 && al1 > bl1)) ? 1.0f : 0.0f;
    eq.y = (he1 && al1 == bl1) ? 1.0f : 0.0f;

    __stcs(out_gt2 + t, gt);
    __stcs(out_eq2 + t, eq);
}

extern "C" void kernel_launch(void* const* d_in, const int* in_sizes, int n_in,
                              void* d_out, int out_size) {
    const float* A = (const float*)d_in[0];
    const float* B = (const float*)d_in[1];
    float* out = (float*)d_out;

    int n_rows = in_sizes[0] / 4;   // (N,4) float32 -> N rows
    int n_units = n_rows / 2;       // 2 rows per thread

    float* out_gt = out;            // [0:N)
    float* out_eq = out + n_rows;   // [N:2N)

    const int threads = 512;
    int blocks = (n_units + threads - 1) / threads;

    comparator4bit_kernel<<<blocks, threads>>>(
        (const uint4*)A, (const uint4*)B,
        (float2*)out_gt, (float2*)out_eq, n_units);
}